// round 6
// baseline (speedup 1.0000x reference)
#include <cuda_runtime.h>
#include <cstdint>
#include <cstddef>

// EdgeEncoder, restructured:
//   Kernel 1 (node_proj): P = tf32(node_emb) @ tf32(W1a) + b1 ; Q = tf32(node_emb) @ tf32(W1b)
//   Kernel 2 (edge):      H = relu(P[u] + Q[v] + sel*w1c) ; out = relu(H @ W2 + b2)
// Math identical to fused form (same tf32 products, fp32 accumulation).
// edge_index is int32.

#define LDX 132   // Xs row stride (floats): conflict-free A-fragment LDS
#define LDW 136   // Ws row stride (floats): conflict-free B-fragment LDS
#define MT  256   // rows per block tile

#define MAXROWS 401408   // >= B*N = 400000, padded
__device__ float P_buf[(size_t)MAXROWS * 128];
__device__ float Q_buf[(size_t)MAXROWS * 128];

__device__ __forceinline__ float f2tf(float f) {
    uint32_t r;
    asm("cvt.rna.tf32.f32 %0, %1;" : "=r"(r) : "f"(f));
    return __uint_as_float(r);
}

__device__ __forceinline__ void mma8(float c[4], const uint32_t a[4], uint32_t b0, uint32_t b1) {
    asm("mma.sync.aligned.m16n8k8.row.col.f32.tf32.tf32.f32 "
        "{%0,%1,%2,%3}, {%4,%5,%6,%7}, {%8,%9}, {%0,%1,%2,%3};"
        : "+f"(c[0]), "+f"(c[1]), "+f"(c[2]), "+f"(c[3])
        : "r"(a[0]), "r"(a[1]), "r"(a[2]), "r"(a[3]), "r"(b0), "r"(b1));
}

// 256x128x128 GEMM: Xs[256][LDX] (tf32 bits) x Ws[128][LDW] -> acc, warp tile 64x64
__device__ __forceinline__ void gemm_pass(const float* __restrict__ Xs,
                                          const float* __restrict__ Ws,
                                          float acc[4][8][4],
                                          int m_warp, int n_warp, int gq, int tq) {
#pragma unroll
    for (int ks = 0; ks < 16; ++ks) {
        const int k0 = ks * 8;
        uint32_t a[4][4];
#pragma unroll
        for (int mt = 0; mt < 4; ++mt) {
            const int r0 = m_warp + mt * 16 + gq;
            a[mt][0] = __float_as_uint(Xs[r0 * LDX + k0 + tq]);
            a[mt][1] = __float_as_uint(Xs[(r0 + 8) * LDX + k0 + tq]);
            a[mt][2] = __float_as_uint(Xs[r0 * LDX + k0 + tq + 4]);
            a[mt][3] = __float_as_uint(Xs[(r0 + 8) * LDX + k0 + tq + 4]);
        }
#pragma unroll
        for (int nt = 0; nt < 8; ++nt) {
            const int n0 = n_warp + nt * 8 + gq;
            const uint32_t bb0 = __float_as_uint(Ws[(k0 + tq) * LDW + n0]);
            const uint32_t bb1 = __float_as_uint(Ws[(k0 + tq + 4) * LDW + n0]);
#pragma unroll
            for (int mt = 0; mt < 4; ++mt) mma8(acc[mt][nt], a[mt], bb0, bb1);
        }
    }
}

__device__ __forceinline__ void zero_acc(float acc[4][8][4]) {
#pragma unroll
    for (int mt = 0; mt < 4; ++mt)
#pragma unroll
        for (int nt = 0; nt < 8; ++nt)
#pragma unroll
            for (int i = 0; i < 4; ++i) acc[mt][nt][i] = 0.f;
}

__device__ __forceinline__ void load_w_tile(float* __restrict__ Ws,
                                            const float* __restrict__ src_f, int tid) {
    const float4* src = reinterpret_cast<const float4*>(src_f);
#pragma unroll
    for (int i = tid; i < 128 * 32; i += 256) {
        const int k = i >> 5, c = i & 31;
        float4 v = src[i];
        float4 w;
        w.x = f2tf(v.x); w.y = f2tf(v.y); w.z = f2tf(v.z); w.w = f2tf(v.w);
        reinterpret_cast<float4*>(Ws + k * LDW + c * 4)[0] = w;
    }
}

// ---------------- Kernel 1: node projections P, Q ----------------
__global__ void __launch_bounds__(256, 1) node_proj_kernel(
    const float* __restrict__ node_emb,
    const float* __restrict__ W1,
    const float* __restrict__ b1,
    int BN)
{
    extern __shared__ float smem[];
    float* Xs  = smem;               // 256*LDX
    float* Ws  = Xs + MT * LDX;      // 128*LDW
    float* b1s = Ws + 128 * LDW;     // 128

    const int tid  = threadIdx.x;
    const int wid  = tid >> 5;
    const int lane = tid & 31;
    const int gq   = lane >> 2;
    const int tq   = lane & 3;
    const int m_warp = (wid & 3) * 64;
    const int n_warp = (wid >> 2) * 64;
    const int gbase = blockIdx.x * MT;

    if (tid < 128) b1s[tid] = b1[tid];

    // Load X tile (1 thread per row), tf32-round into Xs
    {
        int g = gbase + tid;
        if (g >= BN) g = BN - 1;
        const float4* src = reinterpret_cast<const float4*>(node_emb + (size_t)g * 128);
        float* xrow = Xs + tid * LDX;
#pragma unroll
        for (int i = 0; i < 32; ++i) {
            float4 v = src[i];
            float4 w;
            w.x = f2tf(v.x); w.y = f2tf(v.y); w.z = f2tf(v.z); w.w = f2tf(v.w);
            reinterpret_cast<float4*>(xrow + i * 4)[0] = w;
        }
    }
    load_w_tile(Ws, W1, tid);            // W1a
    __syncthreads();

    float acc[4][8][4];
    zero_acc(acc);
    gemm_pass(Xs, Ws, acc, m_warp, n_warp, gq, tq);

    // epilogue P = acc + b1 (32B-sector-aligned float2 stores)
#pragma unroll
    for (int nt = 0; nt < 8; ++nt) {
        const int n0 = n_warp + nt * 8 + tq * 2;
        const float bv0 = b1s[n0], bv1 = b1s[n0 + 1];
#pragma unroll
        for (int mt = 0; mt < 4; ++mt) {
            const int r0 = gbase + m_warp + mt * 16 + gq;
            if (r0 < BN)
                *reinterpret_cast<float2*>(P_buf + (size_t)r0 * 128 + n0) =
                    make_float2(acc[mt][nt][0] + bv0, acc[mt][nt][1] + bv1);
            if (r0 + 8 < BN)
                *reinterpret_cast<float2*>(P_buf + (size_t)(r0 + 8) * 128 + n0) =
                    make_float2(acc[mt][nt][2] + bv0, acc[mt][nt][3] + bv1);
        }
    }
    __syncthreads();                      // gemm reads of Ws done
    load_w_tile(Ws, W1 + 128 * 128, tid); // W1b
    __syncthreads();

    zero_acc(acc);
    gemm_pass(Xs, Ws, acc, m_warp, n_warp, gq, tq);

#pragma unroll
    for (int nt = 0; nt < 8; ++nt) {
        const int n0 = n_warp + nt * 8 + tq * 2;
#pragma unroll
        for (int mt = 0; mt < 4; ++mt) {
            const int r0 = gbase + m_warp + mt * 16 + gq;
            if (r0 < BN)
                *reinterpret_cast<float2*>(Q_buf + (size_t)r0 * 128 + n0) =
                    make_float2(acc[mt][nt][0], acc[mt][nt][1]);
            if (r0 + 8 < BN)
                *reinterpret_cast<float2*>(Q_buf + (size_t)(r0 + 8) * 128 + n0) =
                    make_float2(acc[mt][nt][2], acc[mt][nt][3]);
        }
    }
}

// ---------------- Kernel 2: edge combine + GEMM2 ----------------
__global__ void __launch_bounds__(256, 1) edge_kernel(
    const int* __restrict__ edge_index,
    const float* __restrict__ edge_sel,
    const float* __restrict__ W1,     // for w1c row (row 256)
    const float* __restrict__ W2,
    const float* __restrict__ b2,
    float* __restrict__ out,
    int E, int blocks_per_batch, int n_nodes)
{
    extern __shared__ float smem[];
    float* Xs   = smem;               // 256*LDX
    float* Ws   = Xs + MT * LDX;      // 128*LDW
    float* w1cs = Ws + 128 * LDW;     // 128
    float* b2s  = w1cs + 128;         // 128

    const int tid  = threadIdx.x;
    const int wid  = tid >> 5;
    const int lane = tid & 31;
    const int gq   = lane >> 2;
    const int tq   = lane & 3;
    const int m_warp = (wid & 3) * 64;
    const int n_warp = (wid >> 2) * 64;

    const int b_idx = blockIdx.x / blocks_per_batch;
    const int t     = blockIdx.x - b_idx * blocks_per_batch;
    const long long edge_base = (long long)b_idx * E + (long long)t * MT;

    if (tid < 128) {
        w1cs[tid] = W1[256 * 128 + tid];
        b2s[tid]  = b2[tid];
    }
    load_w_tile(Ws, W2, tid);
    __syncthreads();   // w1cs visible before combine

    // gather + combine: thread r owns edge row r
    {
        const int r = tid;
        const int2 e = reinterpret_cast<const int2*>(edge_index)[edge_base + r];
        int iu = e.x, iv = e.y;
        iu = min(max(iu, 0), n_nodes - 1);
        iv = min(max(iv, 0), n_nodes - 1);
        const float s = edge_sel[edge_base + r];
        const size_t rowbase = (size_t)b_idx * n_nodes;
        const float4* pu = reinterpret_cast<const float4*>(P_buf + (rowbase + iu) * 128);
        const float4* qv = reinterpret_cast<const float4*>(Q_buf + (rowbase + iv) * 128);
        float* xrow = Xs + r * LDX;
#pragma unroll
        for (int i = 0; i < 32; ++i) {
            const float4 a = pu[i];
            const float4 b = qv[i];
            const int k = i * 4;
            float4 w;
            w.x = f2tf(fmaxf(a.x + b.x + s * w1cs[k],     0.f));
            w.y = f2tf(fmaxf(a.y + b.y + s * w1cs[k + 1], 0.f));
            w.z = f2tf(fmaxf(a.z + b.z + s * w1cs[k + 2], 0.f));
            w.w = f2tf(fmaxf(a.w + b.w + s * w1cs[k + 3], 0.f));
            reinterpret_cast<float4*>(xrow + k)[0] = w;
        }
    }
    __syncthreads();

    float acc[4][8][4];
    zero_acc(acc);
    gemm_pass(Xs, Ws, acc, m_warp, n_warp, gq, tq);

    // epilogue: out = relu(acc + b2)
#pragma unroll
    for (int nt = 0; nt < 8; ++nt) {
        const int n0 = n_warp + nt * 8 + tq * 2;
        const float bv0 = b2s[n0], bv1 = b2s[n0 + 1];
#pragma unroll
        for (int mt = 0; mt < 4; ++mt) {
            const int r0 = m_warp + mt * 16 + gq;
            *reinterpret_cast<float2*>(out + (size_t)(edge_base + r0) * 128 + n0) =
                make_float2(fmaxf(acc[mt][nt][0] + bv0, 0.f),
                            fmaxf(acc[mt][nt][1] + bv1, 0.f));
            *reinterpret_cast<float2*>(out + (size_t)(edge_base + r0 + 8) * 128 + n0) =
                make_float2(fmaxf(acc[mt][nt][2] + bv0, 0.f),
                            fmaxf(acc[mt][nt][3] + bv1, 0.f));
        }
    }
}

extern "C" void kernel_launch(void* const* d_in, const int* in_sizes, int n_in,
                              void* d_out, int out_size) {
    const float* node_emb   = (const float*)d_in[0];
    const int*   edge_index = (const int*)d_in[1];   // int32
    const float* edge_sel   = (const float*)d_in[2];
    const float* W1         = (const float*)d_in[3];
    const float* b1         = (const float*)d_in[4];
    const float* W2         = (const float*)d_in[5];
    const float* b2         = (const float*)d_in[6];
    float*       out        = (float*)d_out;

    const int B  = 4;
    const int E  = in_sizes[2] / B;
    const int n_nodes = in_sizes[0] / (B * 128);
    const int BN = B * n_nodes;

    const int grid1 = (BN + MT - 1) / MT;
    const int blocks_per_batch = E / MT;
    const int grid2 = B * blocks_per_batch;

    const size_t smem1 = (size_t)(MT * LDX + 128 * LDW + 128) * sizeof(float);
    const size_t smem2 = (size_t)(MT * LDX + 128 * LDW + 256) * sizeof(float);
    cudaFuncSetAttribute(node_proj_kernel,
                         cudaFuncAttributeMaxDynamicSharedMemorySize, (int)smem1);
    cudaFuncSetAttribute(edge_kernel,
                         cudaFuncAttributeMaxDynamicSharedMemorySize, (int)smem2);

    node_proj_kernel<<<grid1, 256, smem1>>>(node_emb, W1, b1, BN);
    edge_kernel<<<grid2, 256, smem2>>>(edge_index, edge_sel, W1, W2, b2, out,
                                       E, blocks_per_batch, n_nodes);
}

// round 7
// speedup vs baseline: 1.1391x; 1.1391x over previous
#include <cuda_runtime.h>
#include <cstdint>
#include <cstddef>

// EdgeEncoder:
//   K1 (proj):  P = tf32(node_emb)@tf32(W1a) + b1 ; Q = tf32(node_emb)@tf32(W1b)
//   K2 (edge):  persistent + double-buffered pipeline:
//               H = relu(P[u]+Q[v]+sel*w1c) ; out = relu(tf32(H)@tf32(W2) + b2)
// edge_index is int32. Numerics identical to R6 (rel_err ~4.1e-4).

#define LDX 132
#define LDW 136

#define MAXROWS 401408
__device__ float P_buf[(size_t)MAXROWS * 128];
__device__ float Q_buf[(size_t)MAXROWS * 128];

__device__ __forceinline__ float f2tf(float f) {
    uint32_t r;
    asm("cvt.rna.tf32.f32 %0, %1;" : "=r"(r) : "f"(f));
    return __uint_as_float(r);
}

__device__ __forceinline__ void mma8(float c[4], const uint32_t a[4], uint32_t b0, uint32_t b1) {
    asm("mma.sync.aligned.m16n8k8.row.col.f32.tf32.tf32.f32 "
        "{%0,%1,%2,%3}, {%4,%5,%6,%7}, {%8,%9}, {%0,%1,%2,%3};"
        : "+f"(c[0]), "+f"(c[1]), "+f"(c[2]), "+f"(c[3])
        : "r"(a[0]), "r"(a[1]), "r"(a[2]), "r"(a[3]), "r"(b0), "r"(b1));
}

__device__ __forceinline__ void load_w_tile(float* __restrict__ Ws,
                                            const float* __restrict__ src_f,
                                            int tid, int nthr) {
    const float4* src = reinterpret_cast<const float4*>(src_f);
    for (int i = tid; i < 128 * 32; i += nthr) {
        const int k = i >> 5, c = i & 31;
        float4 v = src[i];
        float4 w;
        w.x = f2tf(v.x); w.y = f2tf(v.y); w.z = f2tf(v.z); w.w = f2tf(v.w);
        reinterpret_cast<float4*>(Ws + k * LDW + c * 4)[0] = w;
    }
}

// ================= Kernel 1: node projections (512 thr, 256-row tiles) =================
__global__ void __launch_bounds__(512, 1) node_proj_kernel(
    const float* __restrict__ node_emb,
    const float* __restrict__ W1,
    const float* __restrict__ b1,
    int BN)
{
    extern __shared__ float smem[];
    float* Xs  = smem;               // 256*LDX
    float* Ws  = Xs + 256 * LDX;     // 128*LDW
    float* b1s = Ws + 128 * LDW;     // 128

    const int tid  = threadIdx.x;
    const int wid  = tid >> 5;
    const int lane = tid & 31;
    const int gq   = lane >> 2;
    const int tq   = lane & 3;
    const int m_warp = (wid & 3) * 64;     // 4 m-splits of 64
    const int n_warp = (wid >> 2) * 32;    // 4 n-splits of 32
    const int gbase = blockIdx.x * 256;

    if (tid < 128) b1s[tid] = b1[tid];

    // X tile load: 2 threads/row, bank-rotated STS
    {
        const int r = tid >> 1, h = tid & 1;
        int g = gbase + r;
        if (g >= BN) g = BN - 1;
        const float4* src = reinterpret_cast<const float4*>(node_emb + (size_t)g * 128 + h * 64);
        float* xrow = Xs + r * LDX + h * 64;
#pragma unroll
        for (int j = 0; j < 16; ++j) {
            const int jj = (j + 4 * h) & 15;   // conflict-free phases
            float4 v = src[jj];
            float4 w;
            w.x = f2tf(v.x); w.y = f2tf(v.y); w.z = f2tf(v.z); w.w = f2tf(v.w);
            reinterpret_cast<float4*>(xrow + jj * 4)[0] = w;
        }
    }
    load_w_tile(Ws, W1, tid, 512);           // W1a
    __syncthreads();

    float acc[4][4][4];
#pragma unroll
    for (int mt = 0; mt < 4; ++mt)
#pragma unroll
        for (int nt = 0; nt < 4; ++nt)
#pragma unroll
            for (int i = 0; i < 4; ++i) acc[mt][nt][i] = 0.f;

#pragma unroll
    for (int ks = 0; ks < 16; ++ks) {
        const int k0 = ks * 8;
        uint32_t a[4][4];
#pragma unroll
        for (int mt = 0; mt < 4; ++mt) {
            const int r0 = m_warp + mt * 16 + gq;
            a[mt][0] = __float_as_uint(Xs[r0 * LDX + k0 + tq]);
            a[mt][1] = __float_as_uint(Xs[(r0 + 8) * LDX + k0 + tq]);
            a[mt][2] = __float_as_uint(Xs[r0 * LDX + k0 + tq + 4]);
            a[mt][3] = __float_as_uint(Xs[(r0 + 8) * LDX + k0 + tq + 4]);
        }
#pragma unroll
        for (int nt = 0; nt < 4; ++nt) {
            const int n0 = n_warp + nt * 8 + gq;
            const uint32_t b0 = __float_as_uint(Ws[(k0 + tq) * LDW + n0]);
            const uint32_t b1r = __float_as_uint(Ws[(k0 + tq + 4) * LDW + n0]);
#pragma unroll
            for (int mt = 0; mt < 4; ++mt) mma8(acc[mt][nt], a[mt], b0, b1r);
        }
    }

    // store P = acc + b1
#pragma unroll
    for (int nt = 0; nt < 4; ++nt) {
        const int n0 = n_warp + nt * 8 + tq * 2;
        const float bv0 = b1s[n0], bv1 = b1s[n0 + 1];
#pragma unroll
        for (int mt = 0; mt < 4; ++mt) {
            const int r0 = gbase + m_warp + mt * 16 + gq;
            if (r0 < BN)
                *reinterpret_cast<float2*>(P_buf + (size_t)r0 * 128 + n0) =
                    make_float2(acc[mt][nt][0] + bv0, acc[mt][nt][1] + bv1);
            if (r0 + 8 < BN)
                *reinterpret_cast<float2*>(P_buf + (size_t)(r0 + 8) * 128 + n0) =
                    make_float2(acc[mt][nt][2] + bv0, acc[mt][nt][3] + bv1);
            acc[mt][nt][0] = acc[mt][nt][1] = acc[mt][nt][2] = acc[mt][nt][3] = 0.f;
        }
    }
    __syncthreads();
    load_w_tile(Ws, W1 + 128 * 128, tid, 512);   // W1b
    __syncthreads();

#pragma unroll
    for (int ks = 0; ks < 16; ++ks) {
        const int k0 = ks * 8;
        uint32_t a[4][4];
#pragma unroll
        for (int mt = 0; mt < 4; ++mt) {
            const int r0 = m_warp + mt * 16 + gq;
            a[mt][0] = __float_as_uint(Xs[r0 * LDX + k0 + tq]);
            a[mt][1] = __float_as_uint(Xs[(r0 + 8) * LDX + k0 + tq]);
            a[mt][2] = __float_as_uint(Xs[r0 * LDX + k0 + tq + 4]);
            a[mt][3] = __float_as_uint(Xs[(r0 + 8) * LDX + k0 + tq + 4]);
        }
#pragma unroll
        for (int nt = 0; nt < 4; ++nt) {
            const int n0 = n_warp + nt * 8 + gq;
            const uint32_t b0 = __float_as_uint(Ws[(k0 + tq) * LDW + n0]);
            const uint32_t b1r = __float_as_uint(Ws[(k0 + tq + 4) * LDW + n0]);
#pragma unroll
            for (int mt = 0; mt < 4; ++mt) mma8(acc[mt][nt], a[mt], b0, b1r);
        }
    }
#pragma unroll
    for (int nt = 0; nt < 4; ++nt) {
        const int n0 = n_warp + nt * 8 + tq * 2;
#pragma unroll
        for (int mt = 0; mt < 4; ++mt) {
            const int r0 = gbase + m_warp + mt * 16 + gq;
            if (r0 < BN)
                *reinterpret_cast<float2*>(Q_buf + (size_t)r0 * 128 + n0) =
                    make_float2(acc[mt][nt][0], acc[mt][nt][1]);
            if (r0 + 8 < BN)
                *reinterpret_cast<float2*>(Q_buf + (size_t)(r0 + 8) * 128 + n0) =
                    make_float2(acc[mt][nt][2], acc[mt][nt][3]);
        }
    }
}

// ================= Kernel 2: persistent pipelined edge kernel (256 thr, 64-edge tiles) =================
__global__ void __launch_bounds__(256, 1) edge_kernel(
    const int* __restrict__ edge_index,
    const float* __restrict__ edge_sel,
    const float* __restrict__ W1,
    const float* __restrict__ W2,
    const float* __restrict__ b2,
    float* __restrict__ out,
    int E, int bpb, int n_nodes, int ntiles)
{
    extern __shared__ float smem[];
    float* Xs0  = smem;                 // 64*LDX
    float* Xs1  = Xs0 + 64 * LDX;       // 64*LDX
    float* Ws   = Xs1 + 64 * LDX;       // 128*LDW
    float* w1cs = Ws + 128 * LDW;       // 128
    float* b2s  = w1cs + 128;           // 128

    const int tid  = threadIdx.x;
    const int wid  = tid >> 5;
    const int lane = tid & 31;
    const int gq   = lane >> 2;
    const int tq   = lane & 3;
    const int m_warp = (wid & 1) * 32;     // 2 m-splits
    const int n_warp = (wid >> 1) * 32;    // 4 n-splits
    const int e_loc = tid >> 2;            // edge row 0..63
    const int q     = tid & 3;             // 32-col chunk

    if (tid < 128) {
        w1cs[tid] = W1[256 * 128 + tid];
        b2s[tid]  = b2[tid];
    }
    load_w_tile(Ws, W2, tid, 256);

    const int stride = gridDim.x;
    const int t0 = blockIdx.x;

    // tile -> edge_base
    auto ebase = [&](int t) -> long long {
        const int b = t / bpb;
        return (long long)b * E + (long long)(t - b * bpb) * 64;
    };

    // prefetched state
    int2  idx_c, idx_n;
    float sel_c, sel_n;
    float4 gp[8], gq4[8];

    if (t0 < ntiles) {
        const long long eb = ebase(t0);
        idx_c = reinterpret_cast<const int2*>(edge_index)[eb + e_loc];
        sel_c = edge_sel[eb + e_loc];
        int t1 = t0 + stride; if (t1 >= ntiles) t1 = t0;
        const long long eb1 = ebase(t1);
        idx_n = reinterpret_cast<const int2*>(edge_index)[eb1 + e_loc];
        sel_n = edge_sel[eb1 + e_loc];
        // gather tile t0
        int iu = min(max(idx_c.x, 0), n_nodes - 1);
        int iv = min(max(idx_c.y, 0), n_nodes - 1);
        const size_t rowbase = (size_t)(t0 / bpb) * n_nodes;
        const float4* pu = reinterpret_cast<const float4*>(P_buf + (rowbase + iu) * 128 + q * 32);
        const float4* qv = reinterpret_cast<const float4*>(Q_buf + (rowbase + iv) * 128 + q * 32);
#pragma unroll
        for (int i = 0; i < 8; ++i) { gp[i] = pu[i]; gq4[i] = qv[i]; }
    }
    __syncthreads();

    int cur = 0;
    for (int t = t0; t < ntiles; t += stride) {
        float* Xc = cur ? Xs1 : Xs0;
        const long long eb = ebase(t);

        // ---- combine(t): relu(P+Q+sel*w1c) -> Xc (bank-rotated STS) ----
        {
            const float s = sel_c;
            float* xrow = Xc + e_loc * LDX + q * 32;
            const float4* w1c4 = reinterpret_cast<const float4*>(w1cs + q * 32);
#pragma unroll
            for (int i = 0; i < 8; ++i) {
                const int c4 = (i + 2 * q) & 7;
                const float4 a = gp[c4];
                const float4 b = gq4[c4];
                const float4 w = w1c4[c4];
                float4 r;
                r.x = f2tf(fmaxf(a.x + b.x + s * w.x, 0.f));
                r.y = f2tf(fmaxf(a.y + b.y + s * w.y, 0.f));
                r.z = f2tf(fmaxf(a.z + b.z + s * w.z, 0.f));
                r.w = f2tf(fmaxf(a.w + b.w + s * w.w, 0.f));
                reinterpret_cast<float4*>(xrow + c4 * 4)[0] = r;
            }
        }

        // ---- prefetch idx/sel(t+2s), gather(t+s) ----
        {
            int t2 = t + 2 * stride; if (t2 >= ntiles) t2 = t;
            const long long eb2 = ebase(t2);
            const int2  idx_f = reinterpret_cast<const int2*>(edge_index)[eb2 + e_loc];
            const float sel_f = edge_sel[eb2 + e_loc];

            int t1 = t + stride; if (t1 >= ntiles) t1 = t;
            int iu = min(max(idx_n.x, 0), n_nodes - 1);
            int iv = min(max(idx_n.y, 0), n_nodes - 1);
            const size_t rowbase = (size_t)(t1 / bpb) * n_nodes;
            const float4* pu = reinterpret_cast<const float4*>(P_buf + (rowbase + iu) * 128 + q * 32);
            const float4* qv = reinterpret_cast<const float4*>(Q_buf + (rowbase + iv) * 128 + q * 32);
#pragma unroll
            for (int i = 0; i < 8; ++i) { gp[i] = pu[i]; gq4[i] = qv[i]; }

            idx_n = idx_f; sel_c = sel_n; sel_n = sel_f;
        }

        __syncthreads();

        // ---- GEMM2 on Xc (64x128x128), warp tile 32x32 ----
        float acc[2][4][4];
#pragma unroll
        for (int mt = 0; mt < 2; ++mt)
#pragma unroll
            for (int nt = 0; nt < 4; ++nt)
#pragma unroll
                for (int i = 0; i < 4; ++i) acc[mt][nt][i] = 0.f;

#pragma unroll
        for (int ks = 0; ks < 16; ++ks) {
            const int k0 = ks * 8;
            uint32_t a[2][4];
#pragma unroll
            for (int mt = 0; mt < 2; ++mt) {
                const int r0 = m_warp + mt * 16 + gq;
                a[mt][0] = __float_as_uint(Xc[r0 * LDX + k0 + tq]);
                a[mt][1] = __float_as_uint(Xc[(r0 + 8) * LDX + k0 + tq]);
                a[mt][2] = __float_as_uint(Xc[r0 * LDX + k0 + tq + 4]);
                a[mt][3] = __float_as_uint(Xc[(r0 + 8) * LDX + k0 + tq + 4]);
            }
#pragma unroll
            for (int nt = 0; nt < 4; ++nt) {
                const int n0 = n_warp + nt * 8 + gq;
                const uint32_t b0 = __float_as_uint(Ws[(k0 + tq) * LDW + n0]);
                const uint32_t b1r = __float_as_uint(Ws[(k0 + tq + 4) * LDW + n0]);
                mma8(acc[0][nt], a[0], b0, b1r);
                mma8(acc[1][nt], a[1], b0, b1r);
            }
        }

        // ---- epilogue: out = relu(acc + b2) ----
#pragma unroll
        for (int nt = 0; nt < 4; ++nt) {
            const int n0 = n_warp + nt * 8 + tq * 2;
            const float bv0 = b2s[n0], bv1 = b2s[n0 + 1];
#pragma unroll
            for (int mt = 0; mt < 2; ++mt) {
                const int r0 = m_warp + mt * 16 + gq;
                *reinterpret_cast<float2*>(out + (size_t)(eb + r0) * 128 + n0) =
                    make_float2(fmaxf(acc[mt][nt][0] + bv0, 0.f),
                                fmaxf(acc[mt][nt][1] + bv1, 0.f));
                *reinterpret_cast<float2*>(out + (size_t)(eb + r0 + 8) * 128 + n0) =
                    make_float2(fmaxf(acc[mt][nt][2] + bv0, 0.f),
                                fmaxf(acc[mt][nt][3] + bv1, 0.f));
            }
        }
        cur ^= 1;
    }
}

extern "C" void kernel_launch(void* const* d_in, const int* in_sizes, int n_in,
                              void* d_out, int out_size) {
    const float* node_emb   = (const float*)d_in[0];
    const int*   edge_index = (const int*)d_in[1];   // int32
    const float* edge_sel   = (const float*)d_in[2];
    const float* W1         = (const float*)d_in[3];
    const float* b1         = (const float*)d_in[4];
    const float* W2         = (const float*)d_in[5];
    const float* b2         = (const float*)d_in[6];
    float*       out        = (float*)d_out;

    const int B  = 4;
    const int E  = in_sizes[2] / B;
    const int n_nodes = in_sizes[0] / (B * 128);
    const int BN = B * n_nodes;

    const int grid1 = (BN + 255) / 256;
    const int bpb   = E / 64;
    const int ntiles = B * bpb;

    int dev = 0, sms = 148;
    cudaGetDevice(&dev);
    cudaDeviceGetAttribute(&sms, cudaDevAttrMultiProcessorCount, dev);
    const int grid2 = sms < ntiles ? sms : ntiles;

    const size_t smem1 = (size_t)(256 * LDX + 128 * LDW + 128) * sizeof(float);
    const size_t smem2 = (size_t)(2 * 64 * LDX + 128 * LDW + 256) * sizeof(float);
    cudaFuncSetAttribute(node_proj_kernel,
                         cudaFuncAttributeMaxDynamicSharedMemorySize, (int)smem1);
    cudaFuncSetAttribute(edge_kernel,
                         cudaFuncAttributeMaxDynamicSharedMemorySize, (int)smem2);

    node_proj_kernel<<<grid1, 512, smem1>>>(node_emb, W1, b1, BN);
    edge_kernel<<<grid2, 256, smem2>>>(edge_index, edge_sel, W1, W2, b2, out,
                                       E, bpb, n_nodes, ntiles);
}